// round 15
// baseline (speedup 1.0000x reference)
#include <cuda_runtime.h>
#include <cstdint>

#define NB 2
#define NE 10
#define NC 64
#define NH 128
#define NW 256
#define HW (NH*NW)
#define TW 16
#define CS 68          // scores Xs/Ys stride: conflict-free LDS.128 (4gw pattern)
#define ES (TW*CS)
#define XCS 72         // output Xs stride: conflict-free PAIRED LDS.64 (8g+2tg pattern)
#define XES (TW*XCS)
#define WP 72          // permuted weight-plane stride (hi staging + lo resident)
#define TFMASK 0xffffe000u

// Persistent device scratch (no allocations allowed).
__device__ float d_Mr[NC*NC];          // M[c][cp] = (Wq^T Wk)
__device__ float d_Pr[NC*NC];          // P[d][c]  = (Wo Wv)
__device__ float d_s3[NB*NH*NE*NE];    // axis=3 weights [b][h][i][j]
__device__ float d_s4[NB*NW*NE*NE];    // axis=4 weights [b][w][i][j]

// column permutation: (c, c+4) within each 8-group become adjacent
__device__ __forceinline__ int permc(int c){
    return (c & ~7) | ((c & 3) << 1) | ((c >> 2) & 1);
}

__device__ __forceinline__ uint32_t cvt_tf32(float f){
    uint32_t u; asm("cvt.rna.tf32.f32 %0, %1;" : "=r"(u) : "f"(f)); return u;
}
__device__ __forceinline__ void mma8(float* C, uint32_t a0, uint32_t a1, uint32_t a2, uint32_t a3,
                                     uint32_t b0, uint32_t b1){
    asm volatile("mma.sync.aligned.m16n8k8.row.col.f32.tf32.tf32.f32 "
                 "{%0,%1,%2,%3}, {%4,%5,%6,%7}, {%8,%9}, {%0,%1,%2,%3};"
                 : "+f"(C[0]), "+f"(C[1]), "+f"(C[2]), "+f"(C[3])
                 : "r"(a0), "r"(a1), "r"(a2), "r"(a3), "r"(b0), "r"(b1));
}
__device__ __forceinline__ float gelu_fast(float v){
    float u2 = fmaf(0.0713548162726009f*v, v*v, 1.5957691216057308f*v);  // 2u
    return __fdividef(v, 1.0f + __expf(-u2));
}

// ---------------- prep (+zero) ----------------
__global__ void prep_kernel(const float* __restrict__ Wq, const float* __restrict__ Wk,
                            const float* __restrict__ Wv, const float* __restrict__ Wo){
    int idx = blockIdx.x * blockDim.x + threadIdx.x;
    if (idx < NC*NC){
        int c = idx >> 6, cp = idx & 63;
        float s = 0.f;
        #pragma unroll 8
        for (int d = 0; d < NC; d++) s += Wq[d*NC + c] * Wk[d*NC + cp];
        d_Mr[idx] = s;
    } else if (idx < 2*NC*NC){
        int t = idx - NC*NC;
        int d = t >> 6, c = t & 63;
        float s = 0.f;
        #pragma unroll 8
        for (int e = 0; e < NC; e++) s += Wo[d*NC + e] * Wv[e*NC + c];
        d_Pr[t] = s;
    }
    if (idx < NB*NH*NE*NE) d_s3[idx] = 0.f;
    if (idx < NB*NW*NE*NE) d_s4[idx] = 0.f;
}

// ---- fp32 x tile, natural columns, stride CS (scores) ----
__device__ __forceinline__ void load_x_tile(float* Xs, const float* xb, int tid){
    for (int i = tid; i < NE*NC*(TW/4); i += 256){
        int row = i >> 2, q = i & 3;            // row = e*64+c
        float4 v = *(const float4*)(xb + (size_t)row*HW + q*4);
        int e = row >> 6, c = row & 63;
        float* dst = Xs + (size_t)e*ES + (q*4)*CS + c;
        dst[0]    = v.x; dst[CS]   = v.y;
        dst[2*CS] = v.z; dst[3*CS] = v.w;
    }
}
// ---- fp32 x tile, PERMUTED columns, stride XCS (output) ----
__device__ __forceinline__ void load_x_tile_perm(float* Xs, const float* xb, int tid){
    for (int i = tid; i < NE*NC*(TW/4); i += 256){
        int row = i >> 2, q = i & 3;
        float4 v = *(const float4*)(xb + (size_t)row*HW + q*4);
        int e = row >> 6, c = permc(row & 63);
        float* dst = Xs + (size_t)e*XES + (q*4)*XCS + c;
        dst[0]     = v.x; dst[XCS]   = v.y;
        dst[2*XCS] = v.z; dst[3*XCS] = v.w;
    }
}
// ---- split weight, PERMUTED columns, stride WP: hi -> staging, lo -> resident ----
__device__ __forceinline__ void split_w_perm(float* Whi, float* Wlo, const float* Wsrc, int tid){
    for (int i = tid; i < NC*NC; i += 256){
        int r = i >> 6, c = permc(i & 63);
        float m = Wsrc[i];
        float hi = __uint_as_float(cvt_tf32(m));
        Whi[r*WP + c] = hi;
        Wlo[r*WP + c] = __uint_as_float(cvt_tf32(m - hi));
    }
}
// A-frag hi loads from permuted plane: pairs adjacent -> float2
#define LOAD_AH_P(Ah, Hi, r0, tg)                                                \
    _Pragma("unroll")                                                            \
    for (int k = 0; k < 8; k++){                                                 \
        int co = k*8 + 2*(tg);                                                   \
        float2 hA = *(const float2*)((Hi) +  (r0)   *WP + co);                   \
        float2 hB = *(const float2*)((Hi) + ((r0)+8)*WP + co);                   \
        Ah[k][0] = __float_as_uint(hA.x);                                        \
        Ah[k][1] = __float_as_uint(hB.x);                                        \
        Ah[k][2] = __float_as_uint(hA.y);                                        \
        Ah[k][3] = __float_as_uint(hB.y);                                        \
    }
// A-lo per-k loads from permuted plane: 2x LDS.64, conflict-free (8g+2tg)
#define LOAD_AL_P(Lo, r0, co)                                                    \
        float2 lA = *(const float2*)((Lo) +  (r0)   *WP + (co));                 \
        float2 lB = *(const float2*)((Lo) + ((r0)+8)*WP + (co));                 \
        uint32_t Al0 = __float_as_uint(lA.x);                                    \
        uint32_t Al1 = __float_as_uint(lB.x);                                    \
        uint32_t Al2 = __float_as_uint(lA.y);                                    \
        uint32_t Al3 = __float_as_uint(lB.y);
// 3-term, SCALAR B loads (kc, kc+4) from unpermuted plane, mask split
#define MMA3S(C, k, Bbase)                                                       \
    {   const float* bp = (Bbase);                                               \
        float f0 = bp[0], f1 = bp[4];                                            \
        uint32_t bh0 = __float_as_uint(f0) & TFMASK;                             \
        uint32_t bh1 = __float_as_uint(f1) & TFMASK;                             \
        uint32_t bl0 = __float_as_uint(f0 - __uint_as_float(bh0));               \
        uint32_t bl1 = __float_as_uint(f1 - __uint_as_float(bh1));               \
        mma8(C, Ah[k][0],Ah[k][1],Ah[k][2],Ah[k][3], bh0,bh1);                   \
        mma8(C, Ah[k][0],Ah[k][1],Ah[k][2],Ah[k][3], bl0,bl1);                   \
        mma8(C, Al0,Al1,Al2,Al3, bh0,bh1);                                       \
    }
// 3-term, PAIRED B load (one LDS.64) from permuted plane, mask split
#define MMA3P(C, k, Bpair)                                                       \
    {   float2 bv = *(const float2*)(Bpair);                                     \
        uint32_t bh0 = __float_as_uint(bv.x) & TFMASK;                           \
        uint32_t bh1 = __float_as_uint(bv.y) & TFMASK;                           \
        uint32_t bl0 = __float_as_uint(bv.x - __uint_as_float(bh0));             \
        uint32_t bl1 = __float_as_uint(bv.y - __uint_as_float(bh1));             \
        mma8(C, Ah[k][0],Ah[k][1],Ah[k][2],Ah[k][3], bh0,bh1);                   \
        mma8(C, Ah[k][0],Ah[k][1],Ah[k][2],Ah[k][3], bl0,bl1);                   \
        mma8(C, Al0,Al1,Al2,Al3, bh0,bh1);                                       \
    }

// ---------------- scores: 3 blocks/SM; Xs/Ys natural(68); Mlo permuted(72) -----------
// smem floats: Xs [10][16][68] 43520B | Mlo [64][72] 18432B | Ys [2][16][68] 8704B = 70.7KB
#define SMEM_SCORES ((NE*ES + NC*WP + 2*ES)*4)
__global__ void __launch_bounds__(256, 3) scores_kernel(const float* __restrict__ x){
    extern __shared__ float sm[];
    float* Xs  = sm;
    float* Mlo = sm + NE*ES;
    float* Ys  = Mlo + NC*WP;                 // [jj][w][c]

    const int tid = threadIdx.x, lane = tid & 31, warp = tid >> 5;
    const int b = blockIdx.z, h = blockIdx.y, w0 = blockIdx.x * TW;
    const int g = lane >> 2, tg = lane & 3;
    const int mtile = warp >> 1, npair = warp & 1;
    const int r0 = mtile*16 + g;

    split_w_perm(Xs, Mlo, d_Mr, tid);         // Mhi staged (permuted, WP) in Xs space
    __syncthreads();
    uint32_t Ah[8][4];
    LOAD_AH_P(Ah, Xs, r0, tg)
    __syncthreads();
    load_x_tile(Xs, x + (size_t)b*NE*NC*HW + h*NW + w0, tid);
    __syncthreads();

    for (int jp = 0; jp < NE; jp += 2){
        float C0[4] = {0,0,0,0}, C1[4] = {0,0,0,0};
        const int n0 = npair*16 + g;
        const int n1 = npair*16 + 8 + g;
        const float* B0 = Xs + (size_t)(jp + (n0 >> 4))*ES + (n0 & 15)*CS;
        const float* B1 = Xs + (size_t)(jp + (n1 >> 4))*ES + (n1 & 15)*CS;
        #pragma unroll
        for (int k = 0; k < 8; k++){
            const int kc = k*8 + tg;
            const int co = k*8 + 2*tg;
            LOAD_AL_P(Mlo, r0, co)
            MMA3S(C0, k, B0 + kc)
            MMA3S(C1, k, B1 + kc)
        }
        #pragma unroll
        for (int t = 0; t < 2; t++){
            int n  = (npair*2 + t)*8 + 2*tg;
            float* yb = Ys + (size_t)(n >> 4)*ES + (n & 15)*CS;
            float* C = t ? C1 : C0;
            yb[r0]          = C[0];
            yb[CS + r0]     = C[1];
            yb[r0 + 8]      = C[2];
            yb[CS + r0 + 8] = C[3];
        }
        __syncthreads();

        if (tid < NE*TW){
            const int gi = tid >> 4, gw = tid & 15;
            const float4* xi = (const float4*)(Xs + (size_t)gi*ES + gw*CS);
            const float4* y0 = (const float4*)(Ys + gw*CS);
            const float4* y1 = (const float4*)(Ys + ES + gw*CS);
            float s0 = 0.f, s1 = 0.f;
            #pragma unroll
            for (int m = 0; m < 16; m++){
                float4 xv = xi[m], a = y0[m], c2 = y1[m];
                s0 = fmaf(xv.x, a.x, s0);  s0 = fmaf(xv.y, a.y, s0);
                s0 = fmaf(xv.z, a.z, s0);  s0 = fmaf(xv.w, a.w, s0);
                s1 = fmaf(xv.x, c2.x, s1); s1 = fmaf(xv.y, c2.y, s1);
                s1 = fmaf(xv.z, c2.z, s1); s1 = fmaf(xv.w, c2.w, s1);
            }
            float* s4p = &d_s4[((b*NW + w0 + gw)*NE + gi)*NE + jp];
            atomicAdd(s4p,     s0);
            atomicAdd(s4p + 1, s1);
            #pragma unroll
            for (int off = 8; off; off >>= 1){
                s0 += __shfl_down_sync(0xffffffffu, s0, off, 16);
                s1 += __shfl_down_sync(0xffffffffu, s1, off, 16);
            }
            if (gw == 0){
                float* s3p = &d_s3[((b*NH + h)*NE + gi)*NE + jp];
                atomicAdd(s3p,     s0);
                atomicAdd(s3p + 1, s1);
            }
        }
        __syncthreads();
    }
}

// ---------------- softmax ----------------
__global__ void softmax_kernel(){
    int idx = blockIdx.x * blockDim.x + threadIdx.x;
    float* row; float scale;
    if (idx < NB*NH*NE){ row = d_s3 + idx*NE; scale = 1.0f/128.0f; }
    else {
        int r = idx - NB*NH*NE;
        if (r >= NB*NW*NE) return;
        row = d_s4 + r*NE; scale = rsqrtf(64.0f*128.0f);
    }
    float v[NE], m = -3.4e38f;
    #pragma unroll
    for (int j = 0; j < NE; j++){ v[j] = row[j]*scale; m = fmaxf(m, v[j]); }
    float s = 0.f;
    #pragma unroll
    for (int j = 0; j < NE; j++){ v[j] = expf(v[j] - m); s += v[j]; }
    float inv = 1.0f/s;
    #pragma unroll
    for (int j = 0; j < NE; j++) row[j] = v[j]*inv;
}

// ---------------- output: 3 blocks/SM; Xs PERMUTED(72); paired LDS.64 everywhere ------
// smem floats: Xs [10][16][72] 46080B | Plo [64][72] 18432B | w4s[16][120] 7680B = 72.2KB
#define W3P 12
#define W4P 120
#define SMEM_OUT ((NE*XES + NC*WP + TW*W4P)*4)
__global__ void __launch_bounds__(256, 3) output_kernel(const float* __restrict__ x,
                                                        float* __restrict__ out){
    extern __shared__ float sm[];
    float* Xs  = sm;                          // [e][w][perm(c)] stride 72
    float* Plo = sm + NE*XES;
    float* w4s = Plo + NC*WP;                 // [w][i*12+j]  (w3+w4 fused)

    const int tid = threadIdx.x, lane = tid & 31, warp = tid >> 5;
    const int b = blockIdx.z, h = blockIdx.y, w0 = blockIdx.x * TW;
    const int g = lane >> 2, tg = lane & 3;
    const int whalf = warp >> 2, mtile = warp & 3;
    const int r0   = mtile*16 + g;
    const int pr0  = mtile*16 + ((g & 3) << 1) + (g >> 2);  // perm(r0); perm(r0+8)=pr0+8
    const int wcol = whalf*8 + g;
    const int wa   = whalf*8 + 2*tg;

    split_w_perm(Xs, Plo, d_Pr, tid);         // Phi staged (permuted, WP) in Xs space
    __syncthreads();
    uint32_t Ah[8][4];
    LOAD_AH_P(Ah, Xs, r0, tg)
    __syncthreads();
    // fused combine weights: w4s[w][i][j] = s4[b,w0+w,i,j] + s3[b,h,i,j]
    for (int t = tid; t < TW*NE*NE; t += 256){
        int w = t / (NE*NE), r = t % (NE*NE);
        w4s[w*W4P + (r/NE)*W3P + (r%NE)] =
            d_s4[(size_t)(b*NW + w0)*NE*NE + t] + d_s3[(b*NH + h)*NE*NE + r];
    }
    load_x_tile_perm(Xs, x + (size_t)b*NE*NC*HW + h*NW + w0, tid);
    __syncthreads();

    // U = P * X — all 10 ensembles' C-fragments in registers
    float C[NE][4];
    #pragma unroll
    for (int e = 0; e < NE; e++){ C[e][0]=0.f; C[e][1]=0.f; C[e][2]=0.f; C[e][3]=0.f; }

    #pragma unroll
    for (int k = 0; k < 8; k++){
        const int co = k*8 + 2*tg;
        LOAD_AL_P(Plo, r0, co)
        #pragma unroll
        for (int e = 0; e < NE; e++){
            MMA3P(C[e], k, Xs + (size_t)e*XES + wcol*XCS + co)
        }
    }

    // combine + residual + gelu; fused weights via vector loads, x via perm index
    #pragma unroll
    for (int i = 0; i < NE; i++){
        const float* war = w4s + (size_t) wa   *W4P + i*W3P;
        const float* wbr = w4s + (size_t)(wa+1)*W4P + i*W3P;
        float4 u0 = *(const float4*)war,  u1 = *(const float4*)(war+4);
        float2 u2 = *(const float2*)(war+8);
        float4 v0 = *(const float4*)wbr,  v1 = *(const float4*)(wbr+4);
        float2 v2 = *(const float2*)(wbr+8);
        float cwa[NE] = { u0.x, u0.y, u0.z, u0.w, u1.x, u1.y, u1.z, u1.w, u2.x, u2.y };
        float cwb[NE] = { v0.x, v0.y, v0.z, v0.w, v1.x, v1.y, v1.z, v1.w, v2.x, v2.y };
        const float* xi = Xs + (size_t)i*XES;
        float a0 = 2.f*xi[ wa   *XCS + pr0    ];
        float a1 = 2.f*xi[(wa+1)*XCS + pr0    ];
        float a2 = 2.f*xi[ wa   *XCS + pr0 + 8];
        float a3 = 2.f*xi[(wa+1)*XCS + pr0 + 8];
        #pragma unroll
        for (int j = 0; j < NE; j++){
            a0 = fmaf(cwa[j], C[j][0], a0);
            a1 = fmaf(cwb[j], C[j][1], a1);
            a2 = fmaf(cwa[j], C[j][2], a2);
            a3 = fmaf(cwb[j], C[j][3], a3);
        }
        float* op = out + ((size_t)(b*NE + i)*NC + r0)*HW + h*NW + w0 + wa;
        *(float2*)op          = make_float2(gelu_fast(a0), gelu_fast(a1));
        *(float2*)(op + 8*HW) = make_float2(gelu_fast(a2), gelu_fast(a3));
    }
}

// ---------------- launch ----------------
extern "C" void kernel_launch(void* const* d_in, const int* in_sizes, int n_in,
                              void* d_out, int out_size){
    const float* x  = (const float*)d_in[0];
    const float* Wv = (const float*)d_in[1];
    const float* Wk = (const float*)d_in[2];
    const float* Wq = (const float*)d_in[3];
    const float* Wo = (const float*)d_in[4];
    float* out = (float*)d_out;

    cudaFuncSetAttribute(scores_kernel, cudaFuncAttributeMaxDynamicSharedMemorySize, SMEM_SCORES);
    cudaFuncSetAttribute(output_kernel, cudaFuncAttributeMaxDynamicSharedMemorySize, SMEM_OUT);

    prep_kernel<<<(NB*NW*NE*NE + 255)/256, 256>>>(Wq, Wk, Wv, Wo);

    dim3 grid(NW/TW, NH, NB);
    scores_kernel<<<grid, 256, SMEM_SCORES>>>(x);
    softmax_kernel<<<(NB*NH*NE + NB*NW*NE + 255)/256, 256>>>();
    output_kernel<<<grid, 256, SMEM_OUT>>>(x, out);
}

// round 16
// speedup vs baseline: 1.1789x; 1.1789x over previous
#include <cuda_runtime.h>
#include <cstdint>

#define NB 2
#define NE 10
#define NC 64
#define NH 128
#define NW 256
#define HW (NH*NW)
#define TW 16
#define CS 68          // stride (floats): conflict-free LDS.128 + scalar frag loads
#define ES (TW*CS)     // per-ensemble plane stride = 1088 floats
#define MPAD 68        // weight plane row stride (scores)
#define TFMASK 0xffffe000u

// Persistent device scratch (no allocations allowed).
__device__ float d_Mr[NC*NC];          // M[c][cp] = (Wq^T Wk)
__device__ float d_Pr[NC*NC];          // P[d][c]  = (Wo Wv)
__device__ float d_s3[NB*NH*NE*NE];    // axis=3 weights [b][h][i][j]
__device__ float d_s4[NB*NW*NE*NE];    // axis=4 weights [b][w][i][j]
// P fragment tables for output kernel: [mtile][k][lane] -> (P[r0][kc], P[r0+8][kc],
// P[r0][kc+4], P[r0+8][kc+4]) split into tf32 hi (RNA) and lo. 16 KB each.
__device__ float4 d_Phif[4*8*32];
__device__ float4 d_Plof[4*8*32];

__device__ __forceinline__ uint32_t cvt_tf32(float f){
    uint32_t u; asm("cvt.rna.tf32.f32 %0, %1;" : "=r"(u) : "f"(f)); return u;
}
__device__ __forceinline__ void mma8(float* C, uint32_t a0, uint32_t a1, uint32_t a2, uint32_t a3,
                                     uint32_t b0, uint32_t b1){
    asm volatile("mma.sync.aligned.m16n8k8.row.col.f32.tf32.tf32.f32 "
                 "{%0,%1,%2,%3}, {%4,%5,%6,%7}, {%8,%9}, {%0,%1,%2,%3};"
                 : "+f"(C[0]), "+f"(C[1]), "+f"(C[2]), "+f"(C[3])
                 : "r"(a0), "r"(a1), "r"(a2), "r"(a3), "r"(b0), "r"(b1));
}
__device__ __forceinline__ float gelu_fast(float v){
    float u2 = fmaf(0.0713548162726009f*v, v*v, 1.5957691216057308f*v);  // 2u
    return __fdividef(v, 1.0f + __expf(-u2));
}

// ---------------- prep (+zero) ----------------
__global__ void prep_kernel(const float* __restrict__ Wq, const float* __restrict__ Wk,
                            const float* __restrict__ Wv, const float* __restrict__ Wo){
    int idx = blockIdx.x * blockDim.x + threadIdx.x;
    if (idx < NC*NC){
        int c = idx >> 6, cp = idx & 63;
        float s = 0.f;
        #pragma unroll 8
        for (int d = 0; d < NC; d++) s += Wq[d*NC + c] * Wk[d*NC + cp];
        d_Mr[idx] = s;
    } else if (idx < 2*NC*NC){
        int t = idx - NC*NC;
        int d = t >> 6, c = t & 63;
        float s = 0.f;
        #pragma unroll 8
        for (int e = 0; e < NC; e++) s += Wo[d*NC + e] * Wv[e*NC + c];
        d_Pr[t] = s;
    }
    if (idx < NB*NH*NE*NE) d_s3[idx] = 0.f;
    if (idx < NB*NW*NE*NE) d_s4[idx] = 0.f;
}

// ---------------- prep2: build P fragment tables (after d_Pr is final) ----------------
__global__ void prepfrag_kernel(){
    int t = blockIdx.x * blockDim.x + threadIdx.x;
    if (t >= 4*8*32) return;
    int lane = t & 31, kk = (t >> 5) & 7, mtile = t >> 8;
    int g = lane >> 2, tg = lane & 3;
    int r0 = mtile*16 + g, kc = kk*8 + tg;
    float m0 = d_Pr[ r0   *NC + kc    ];
    float m1 = d_Pr[(r0+8)*NC + kc    ];
    float m2 = d_Pr[ r0   *NC + kc + 4];
    float m3 = d_Pr[(r0+8)*NC + kc + 4];
    float4 hi, lo;
    hi.x = __uint_as_float(cvt_tf32(m0)); lo.x = __uint_as_float(cvt_tf32(m0 - hi.x));
    hi.y = __uint_as_float(cvt_tf32(m1)); lo.y = __uint_as_float(cvt_tf32(m1 - hi.y));
    hi.z = __uint_as_float(cvt_tf32(m2)); lo.z = __uint_as_float(cvt_tf32(m2 - hi.z));
    hi.w = __uint_as_float(cvt_tf32(m3)); lo.w = __uint_as_float(cvt_tf32(m3 - hi.w));
    d_Phif[t] = hi;
    d_Plof[t] = lo;
}

// ---- fp32 x tile load (layout [e][w][c]) ----
__device__ __forceinline__ void load_x_tile(float* Xs, const float* xb, int tid){
    for (int i = tid; i < NE*NC*(TW/4); i += 256){
        int row = i >> 2, q = i & 3;            // row = e*64+c
        float4 v = *(const float4*)(xb + (size_t)row*HW + q*4);
        int e = row >> 6, c = row & 63;
        float* dst = Xs + (size_t)e*ES + (q*4)*CS + c;
        dst[0]    = v.x; dst[CS]   = v.y;
        dst[2*CS] = v.z; dst[3*CS] = v.w;
    }
}
// ---- split 64x64 weight: hi -> staging, lo -> resident plane (scores only) ----
__device__ __forceinline__ void split_w(float* Whi, float* Wlo, const float* Wsrc, int tid){
    for (int i = tid; i < NC*NC; i += 256){
        int r = i >> 6, c = i & 63;
        float m = Wsrc[i];
        float hi = __uint_as_float(cvt_tf32(m));
        Whi[r*MPAD + c] = hi;
        Wlo[r*MPAD + c] = __uint_as_float(cvt_tf32(m - hi));
    }
}
#define LOAD_AH(Ah, Hi, r0, tg)                                                  \
    _Pragma("unroll")                                                            \
    for (int k = 0; k < 8; k++){                                                 \
        int kc = k*8 + (tg);                                                     \
        Ah[k][0] = __float_as_uint(Hi[ (r0)   *MPAD + kc    ]);                  \
        Ah[k][1] = __float_as_uint(Hi[((r0)+8)*MPAD + kc    ]);                  \
        Ah[k][2] = __float_as_uint(Hi[ (r0)   *MPAD + kc + 4]);                  \
        Ah[k][3] = __float_as_uint(Hi[((r0)+8)*MPAD + kc + 4]);                  \
    }
// 3-term, scalar conflict-free B loads (kc, kc+4), mask split, A from arrays
#define MMA3S(C, k, Bbase)                                                       \
    {   const float* bp = (Bbase);                                               \
        float f0 = bp[0], f1 = bp[4];                                            \
        uint32_t bh0 = __float_as_uint(f0) & TFMASK;                             \
        uint32_t bh1 = __float_as_uint(f1) & TFMASK;                             \
        uint32_t bl0 = __float_as_uint(f0 - __uint_as_float(bh0));               \
        uint32_t bl1 = __float_as_uint(f1 - __uint_as_float(bh1));               \
        mma8(C, Ah[k][0],Ah[k][1],Ah[k][2],Ah[k][3], bh0,bh1);                   \
        mma8(C, Ah[k][0],Ah[k][1],Ah[k][2],Ah[k][3], bl0,bl1);                   \
        mma8(C, Al0,Al1,Al2,Al3, bh0,bh1);                                       \
    }
// 3-term, A operands from explicit registers (output kernel)
#define MMA3G(C, Bbase)                                                          \
    {   const float* bp = (Bbase);                                               \
        float f0 = bp[0], f1 = bp[4];                                            \
        uint32_t bh0 = __float_as_uint(f0) & TFMASK;                             \
        uint32_t bh1 = __float_as_uint(f1) & TFMASK;                             \
        uint32_t bl0 = __float_as_uint(f0 - __uint_as_float(bh0));               \
        uint32_t bl1 = __float_as_uint(f1 - __uint_as_float(bh1));               \
        mma8(C, Ah0,Ah1,Ah2,Ah3, bh0,bh1);                                       \
        mma8(C, Ah0,Ah1,Ah2,Ah3, bl0,bl1);                                       \
        mma8(C, Al0,Al1,Al2,Al3, bh0,bh1);                                       \
    }

// ---------------- scores: 3 blocks/SM (UNCHANGED from the 466.8us R14) ----------------
// smem floats: Xs [10][16][68] | Mlo [64][68] | Ys [2][16][68]  = 68KB
#define SMEM_SCORES ((NE*ES + NC*MPAD + 2*ES)*4)
__global__ void __launch_bounds__(256, 3) scores_kernel(const float* __restrict__ x){
    extern __shared__ float sm[];
    float* Xs  = sm;
    float* Mlo = sm + NE*ES;
    float* Ys  = Mlo + NC*MPAD;               // [jj][w][c]

    const int tid = threadIdx.x, lane = tid & 31, warp = tid >> 5;
    const int b = blockIdx.z, h = blockIdx.y, w0 = blockIdx.x * TW;
    const int g = lane >> 2, tg = lane & 3;
    const int mtile = warp >> 1, npair = warp & 1;
    const int r0 = mtile*16 + g;

    split_w(Xs, Mlo, d_Mr, tid);              // Mhi staged in Xs space
    __syncthreads();
    uint32_t Ah[8][4];
    LOAD_AH(Ah, Xs, r0, tg)
    __syncthreads();
    load_x_tile(Xs, x + (size_t)b*NE*NC*HW + h*NW + w0, tid);
    __syncthreads();

    for (int jp = 0; jp < NE; jp += 2){
        float C0[4] = {0,0,0,0}, C1[4] = {0,0,0,0};
        const int n0 = npair*16 + g;
        const int n1 = npair*16 + 8 + g;
        const float* B0 = Xs + (size_t)(jp + (n0 >> 4))*ES + (n0 & 15)*CS;
        const float* B1 = Xs + (size_t)(jp + (n1 >> 4))*ES + (n1 & 15)*CS;
        #pragma unroll
        for (int k = 0; k < 8; k++){
            const int kc = k*8 + tg;
            uint32_t Al0 = __float_as_uint(Mlo[ r0   *MPAD + kc    ]);
            uint32_t Al1 = __float_as_uint(Mlo[(r0+8)*MPAD + kc    ]);
            uint32_t Al2 = __float_as_uint(Mlo[ r0   *MPAD + kc + 4]);
            uint32_t Al3 = __float_as_uint(Mlo[(r0+8)*MPAD + kc + 4]);
            MMA3S(C0, k, B0 + kc)
            MMA3S(C1, k, B1 + kc)
        }
        #pragma unroll
        for (int t = 0; t < 2; t++){
            int n  = (npair*2 + t)*8 + 2*tg;
            float* yb = Ys + (size_t)(n >> 4)*ES + (n & 15)*CS;
            float* C = t ? C1 : C0;
            yb[r0]          = C[0];
            yb[CS + r0]     = C[1];
            yb[r0 + 8]      = C[2];
            yb[CS + r0 + 8] = C[3];
        }
        __syncthreads();

        if (tid < NE*TW){
            const int gi = tid >> 4, gw = tid & 15;
            const float4* xi = (const float4*)(Xs + (size_t)gi*ES + gw*CS);
            const float4* y0 = (const float4*)(Ys + gw*CS);
            const float4* y1 = (const float4*)(Ys + ES + gw*CS);
            float s0 = 0.f, s1 = 0.f;
            #pragma unroll
            for (int m = 0; m < 16; m++){
                float4 xv = xi[m], a = y0[m], c2 = y1[m];
                s0 = fmaf(xv.x, a.x, s0);  s0 = fmaf(xv.y, a.y, s0);
                s0 = fmaf(xv.z, a.z, s0);  s0 = fmaf(xv.w, a.w, s0);
                s1 = fmaf(xv.x, c2.x, s1); s1 = fmaf(xv.y, c2.y, s1);
                s1 = fmaf(xv.z, c2.z, s1); s1 = fmaf(xv.w, c2.w, s1);
            }
            float* s4p = &d_s4[((b*NW + w0 + gw)*NE + gi)*NE + jp];
            atomicAdd(s4p,     s0);
            atomicAdd(s4p + 1, s1);
            #pragma unroll
            for (int off = 8; off; off >>= 1){
                s0 += __shfl_down_sync(0xffffffffu, s0, off, 16);
                s1 += __shfl_down_sync(0xffffffffu, s1, off, 16);
            }
            if (gw == 0){
                float* s3p = &d_s3[((b*NH + h)*NE + gi)*NE + jp];
                atomicAdd(s3p,     s0);
                atomicAdd(s3p + 1, s1);
            }
        }
        __syncthreads();
    }
}

// ---------------- softmax ----------------
__global__ void softmax_kernel(){
    int idx = blockIdx.x * blockDim.x + threadIdx.x;
    float* row; float scale;
    if (idx < NB*NH*NE){ row = d_s3 + idx*NE; scale = 1.0f/128.0f; }
    else {
        int r = idx - NB*NH*NE;
        if (r >= NB*NW*NE) return;
        row = d_s4 + r*NE; scale = rsqrtf(64.0f*128.0f);
    }
    float v[NE], m = -3.4e38f;
    #pragma unroll
    for (int j = 0; j < NE; j++){ v[j] = row[j]*scale; m = fmaxf(m, v[j]); }
    float s = 0.f;
    #pragma unroll
    for (int j = 0; j < NE; j++){ v[j] = expf(v[j] - m); s += v[j]; }
    float inv = 1.0f/s;
    #pragma unroll
    for (int j = 0; j < NE; j++) row[j] = v[j]*inv;
}

// ---------------- output: 4 blocks/SM; A-frags via coalesced LDG from tables ----------
// smem floats: Xs 43520B | w4s[16][120] 7680B = 51.2KB ; regs target 64
#define W3P 12
#define W4P 120
#define SMEM_OUT ((NE*ES + TW*W4P)*4)
__global__ void __launch_bounds__(256, 4) output_kernel(const float* __restrict__ x,
                                                        float* __restrict__ out){
    extern __shared__ float sm[];
    float* Xs  = sm;                          // [e][w][c] fp32
    float* w4s = sm + NE*ES;                  // [w][i*12+j]  (w3+w4 fused)

    const int tid = threadIdx.x, lane = tid & 31, warp = tid >> 5;
    const int b = blockIdx.z, h = blockIdx.y, w0 = blockIdx.x * TW;
    const int g = lane >> 2, tg = lane & 3;
    const int whalf = warp >> 2, mtile = warp & 3;
    const int r0   = mtile*16 + g;
    const int wcol = whalf*8 + g;
    const int wa   = whalf*8 + 2*tg;

    // fused combine weights: w4s[w][i][j] = s4[b,w0+w,i,j] + s3[b,h,i,j]
    for (int t = tid; t < TW*NE*NE; t += 256){
        int w = t / (NE*NE), r = t % (NE*NE);
        w4s[w*W4P + (r/NE)*W3P + (r%NE)] =
            d_s4[(size_t)(b*NW + w0)*NE*NE + t] + d_s3[(b*NH + h)*NE*NE + r];
    }
    load_x_tile(Xs, x + (size_t)b*NE*NC*HW + h*NW + w0, tid);
    __syncthreads();                          // the only barrier

    // U = P * X — all 10 ensembles' C-fragments in registers
    float C[NE][4];
    #pragma unroll
    for (int e = 0; e < NE; e++){ C[e][0]=0.f; C[e][1]=0.f; C[e][2]=0.f; C[e][3]=0.f; }

    #pragma unroll
    for (int k = 0; k < 8; k++){
        const int kc = k*8 + tg;
        const int fidx = (mtile*8 + k)*32 + lane;
        float4 ah4 = __ldg(&d_Phif[fidx]);    // coalesced LDG.128, L1-hot
        float4 al4 = __ldg(&d_Plof[fidx]);
        uint32_t Ah0 = __float_as_uint(ah4.x), Ah1 = __float_as_uint(ah4.y);
        uint32_t Ah2 = __float_as_uint(ah4.z), Ah3 = __float_as_uint(ah4.w);
        uint32_t Al0 = __float_as_uint(al4.x), Al1 = __float_as_uint(al4.y);
        uint32_t Al2 = __float_as_uint(al4.z), Al3 = __float_as_uint(al4.w);
        #pragma unroll
        for (int e = 0; e < NE; e++){
            MMA3G(C[e], Xs + (size_t)e*ES + wcol*CS + kc)
        }
    }

    // combine + residual + gelu; fused weights via vector loads, x exact fp32
    #pragma unroll
    for (int i = 0; i < NE; i++){
        const float* war = w4s + (size_t) wa   *W4P + i*W3P;
        const float* wbr = w4s + (size_t)(wa+1)*W4P + i*W3P;
        float4 u0 = *(const float4*)war,  u1 = *(const float4*)(war+4);
        float2 u2 = *(const float2*)(war+8);
        float4 v0 = *(const float4*)wbr,  v1 = *(const float4*)(wbr+4);
        float2 v2 = *(const float2*)(wbr+8);
        float cwa[NE] = { u0.x, u0.y, u0.z, u0.w, u1.x, u1.y, u1.z, u1.w, u2.x, u2.y };
        float cwb[NE] = { v0.x, v0.y, v0.z, v0.w, v1.x, v1.y, v1.z, v1.w, v2.x, v2.y };
        const float* xi = Xs + (size_t)i*ES;
        float a0 = 2.f*xi[ wa   *CS + r0    ];
        float a1 = 2.f*xi[(wa+1)*CS + r0    ];
        float a2 = 2.f*xi[ wa   *CS + r0 + 8];
        float a3 = 2.f*xi[(wa+1)*CS + r0 + 8];
        #pragma unroll
        for (int j = 0; j < NE; j++){
            a0 = fmaf(cwa[j], C[j][0], a0);
            a1 = fmaf(cwb[j], C[j][1], a1);
            a2 = fmaf(cwa[j], C[j][2], a2);
            a3 = fmaf(cwb[j], C[j][3], a3);
        }
        float* op = out + ((size_t)(b*NE + i)*NC + r0)*HW + h*NW + w0 + wa;
        *(float2*)op          = make_float2(gelu_fast(a0), gelu_fast(a1));
        *(float2*)(op + 8*HW) = make_float2(gelu_fast(a2), gelu_fast(a3));
    }
}

// ---------------- launch ----------------
extern "C" void kernel_launch(void* const* d_in, const int* in_sizes, int n_in,
                              void* d_out, int out_size){
    const float* x  = (const float*)d_in[0];
    const float* Wv = (const float*)d_in[1];
    const float* Wk = (const float*)d_in[2];
    const float* Wq = (const float*)d_in[3];
    const float* Wo = (const float*)d_in[4];
    float* out = (float*)d_out;

    cudaFuncSetAttribute(scores_kernel, cudaFuncAttributeMaxDynamicSharedMemorySize, SMEM_SCORES);
    cudaFuncSetAttribute(output_kernel, cudaFuncAttributeMaxDynamicSharedMemorySize, SMEM_OUT);

    prep_kernel<<<(NB*NW*NE*NE + 255)/256, 256>>>(Wq, Wk, Wv, Wo);
    prepfrag_kernel<<<4, 256>>>();

    dim3 grid(NW/TW, NH, NB);
    scores_kernel<<<grid, 256, SMEM_SCORES>>>(x);
    softmax_kernel<<<(NB*NH*NE + NB*NW*NE + 255)/256, 256>>>();
    output_kernel<<<grid, 256, SMEM_OUT>>>(x, out);
}